// round 10
// baseline (speedup 1.0000x reference)
#include <cuda_runtime.h>

#define Bn 128
#define Dn 2048
#define Pn 16000
#define Wn 32
#define NCHUNK (Pn / Wn)   // 500

// ---------------- scratch (static device globals; no allocation) ----------------
__device__ int   g_idx[2 * Dn];
__device__ float g_sgn[2 * Dn];
__device__ int   g_c1s[Dn], g_j1[Dn];
__device__ int   g_c2s[Dn], g_j2[Dn];
__device__ float g_U[Dn * Bn];   // [j_sorted][b]
__device__ float g_V[Dn * Bn];   // [i_sorted][b]

// ---------------- kernel 1: find the single nonzero of each C row ----------------
__global__ void k_extract(const float* __restrict__ C1, const float* __restrict__ C2)
{
    int r = blockIdx.x;                       // 0..4095 : C1 rows then C2 rows
    const float* row = (r < Dn) ? (C1 + (size_t)r * Pn)
                                : (C2 + (size_t)(r - Dn) * Pn);
    const float4* row4 = (const float4*)row;  // Pn = 16000 -> 4000 float4, aligned
    int found = -1; float s = 0.f;
    for (int i = threadIdx.x; i < Pn / 4; i += blockDim.x) {
        float4 v = __ldg(row4 + i);
        if (v.x != 0.f) { found = 4 * i + 0; s = v.x; }
        if (v.y != 0.f) { found = 4 * i + 1; s = v.y; }
        if (v.z != 0.f) { found = 4 * i + 2; s = v.z; }
        if (v.w != 0.f) { found = 4 * i + 3; s = v.w; }
    }
    if (found >= 0) { g_idx[r] = found; g_sgn[r] = s; }   // exactly one thread hits
}

// ---------------- kernel 2: bitonic sort of (idx value, d) ----------------
__global__ void k_sort()
{
    __shared__ int key[Dn];
    int base = blockIdx.x * Dn;               // block 0: C1, block 1: C2
    for (int i = threadIdx.x; i < Dn; i += blockDim.x)
        key[i] = (g_idx[base + i] << 11) | i; // idx<16000 (14b) | d (11b)
    __syncthreads();
    for (int size = 2; size <= Dn; size <<= 1)
        for (int stride = size >> 1; stride > 0; stride >>= 1) {
            for (int t = threadIdx.x; t < Dn; t += blockDim.x) {
                int p = t ^ stride;
                if (p > t) {
                    int a = key[t], c = key[p];
                    bool asc = ((t & size) == 0);
                    if ((a > c) == asc) { key[t] = c; key[p] = a; }
                }
            }
            __syncthreads();
        }
    for (int i = threadIdx.x; i < Dn; i += blockDim.x) {
        int kv = key[i];
        if (blockIdx.x == 0) { g_c1s[i] = kv >> 11; g_j1[i] = kv & (Dn - 1); }
        else                 { g_c2s[i] = kv >> 11; g_j2[i] = kv & (Dn - 1); }
    }
}

// ---------------- kernel 3: build signed, sorted, b-contiguous U / V ----------------
__global__ void k_buildUV(const float* __restrict__ x1, const float* __restrict__ x2)
{
    int j = blockIdx.x;                       // 0..4095
    int b = threadIdx.x;                      // 0..127
    if (j < Dn) {
        int d = g_j1[j];
        g_U[j * Bn + b] = g_sgn[d] * __ldg(x1 + b * Dn + d);
    } else {
        int jj = j - Dn;
        int d = g_j2[jj];
        g_V[jj * Bn + b] = g_sgn[Dn + d] * __ldg(x2 + b * Dn + d);
    }
}

// ---------------- kernel 4: sparse-pair circular-convolution, k-chunked ----------------
// Static smem = 16512 + 8192 + 8192 + 4096 + 4096 = 41088 B -> 5 CTAs/SM,
// all 500 CTAs co-resident (single wave, no tail).
__global__ void __launch_bounds__(128) k_main(float* __restrict__ out)
{
    __shared__ float sphi[Wn * 129];          // stride 129: bank-conflict-free both phases
    __shared__ int   sc1[Dn];
    __shared__ int   sc2[Dn];
    __shared__ unsigned short slo[Dn];
    __shared__ unsigned short scnt[Dn];

    int tid = threadIdx.x;                    // tid == batch index b
    int k0  = blockIdx.x * Wn;

    for (int i = tid; i < Wn * 129; i += 128) sphi[i] = 0.f;
    for (int i = tid; i < Dn; i += 128) { sc1[i] = g_c1s[i]; sc2[i] = g_c2s[i]; }
    __syncthreads();

    // Per-d window of sorted-c2 entries landing in [k0, k0+Wn): parallel binary searches
    for (int j = tid; j < Dn; j += 128) {
        int a = k0 - sc1[j]; if (a < 0) a += Pn;      // window start value (mod P)
        int lo = 0, hi = Dn;
        while (lo < hi) { int m = (lo + hi) >> 1; if (sc2[m] < a) lo = m + 1; else hi = m; }
        int cnt;
        if (a + Wn <= Pn) {                           // window [a, a+Wn) does not wrap P
            int lo2 = 0, hi2 = Dn; int x = a + Wn;
            while (lo2 < hi2) { int m = (lo2 + hi2) >> 1; if (sc2[m] < x) lo2 = m + 1; else hi2 = m; }
            cnt = lo2 - lo;
        } else {                                      // window wraps past P
            int lo2 = 0, hi2 = Dn; int x = a + Wn - Pn;
            while (lo2 < hi2) { int m = (lo2 + hi2) >> 1; if (sc2[m] < x) lo2 = m + 1; else hi2 = m; }
            cnt = (Dn - lo) + lo2;
        }
        slo[j]  = (unsigned short)lo;
        scnt[j] = (unsigned short)cnt;
    }
    __syncthreads();

    // Main accumulation: every thread owns batch row b=tid -> race-free smem RMW.
    // Circular run [st, st+cnt) mod Dn split into two LINEAR segments: no per-pair
    // modular index math, clean affine addressing, unrollable.
    const float* __restrict__ Ub = g_U + tid;
    const float* __restrict__ Vb = g_V + tid;
    for (int j = 0; j < Dn; j++) {
        int cnt = scnt[j];
        if (cnt == 0) continue;
        float u   = __ldg(Ub + j * Bn);       // coalesced 128B warp load
        int   st  = slo[j];
        int   c1v = sc1[j];

        int lenA = Dn - st; if (lenA > cnt) lenA = cnt;   // segment A: [st, st+lenA)
        #pragma unroll 2
        for (int i = st; i < st + lenA; i++) {
            float v  = __ldg(Vb + i * Bn);    // coalesced; L1-resident via sorted order
            int kk   = c1v + sc2[i];          // warp-uniform
            if (kk >= Pn) kk -= Pn;           // in [k0, k0+Wn) by window selection
            sphi[(kk - k0) * 129 + tid] += u * v;
        }
        int lenB = cnt - lenA;                            // segment B: [0, lenB)
        #pragma unroll 2
        for (int i = 0; i < lenB; i++) {
            float v  = __ldg(Vb + i * Bn);
            int kk   = c1v + sc2[i];
            if (kk >= Pn) kk -= Pn;
            sphi[(kk - k0) * 129 + tid] += u * v;
        }
    }
    __syncthreads();

    // Transposed, coalesced writeback: lanes sweep consecutive k within a batch row
    for (int r = 0; r < 32; r++) {
        int b2   = (tid >> 5) + (r << 2);     // 0..127, bijective over (r, warpid)
        int krel = tid & 31;
        out[b2 * Pn + k0 + krel] = sphi[krel * 129 + b2];
    }
}

// ---------------- launch ----------------
extern "C" void kernel_launch(void* const* d_in, const int* in_sizes, int n_in,
                              void* d_out, int out_size)
{
    // Identify inputs by element count, preserving relative order:
    // x1/x2 have B*D = 262144, C1/C2 have D*P = 32768000.
    const float* xs[2] = {nullptr, nullptr};
    const float* Cs[2] = {nullptr, nullptr};
    int nx = 0, nc = 0;
    for (int i = 0; i < n_in; i++) {
        if (in_sizes[i] == Bn * Dn) { if (nx < 2) xs[nx++] = (const float*)d_in[i]; }
        else                        { if (nc < 2) Cs[nc++] = (const float*)d_in[i]; }
    }

    k_extract<<<2 * Dn, 256>>>(Cs[0], Cs[1]);
    k_sort<<<2, 1024>>>();
    k_buildUV<<<2 * Dn, Bn>>>(xs[0], xs[1]);
    k_main<<<NCHUNK, 128>>>((float*)d_out);
}

// round 11
// speedup vs baseline: 2.4877x; 2.4877x over previous
#include <cuda_runtime.h>

#define Bn 128
#define Dn 2048
#define Pn 16000
#define Wn 16
#define NCHUNK (Pn / Wn)   // 1000
#define BCAP 416           // per-krel bucket capacity: Poisson(262)+9.5 sigma

// ---------------- scratch (static device globals; no allocation) ----------------
__device__ int   g_idx[2 * Dn];
__device__ float g_sgn[2 * Dn];
__device__ int   g_c1s[Dn], g_j1[Dn];
__device__ int   g_c2s[Dn], g_j2[Dn];
__device__ float g_U[Dn * Bn];   // [j_sorted][b]
__device__ float g_V[Dn * Bn];   // [i_sorted][b]

// ---------------- kernel 1: find the single nonzero of each C row ----------------
__global__ void k_extract(const float* __restrict__ C1, const float* __restrict__ C2)
{
    int r = blockIdx.x;                       // 0..4095 : C1 rows then C2 rows
    const float* row = (r < Dn) ? (C1 + (size_t)r * Pn)
                                : (C2 + (size_t)(r - Dn) * Pn);
    const float4* row4 = (const float4*)row;  // Pn = 16000 -> 4000 float4, aligned
    int found = -1; float s = 0.f;
    for (int i = threadIdx.x; i < Pn / 4; i += blockDim.x) {
        float4 v = __ldg(row4 + i);
        if (v.x != 0.f) { found = 4 * i + 0; s = v.x; }
        if (v.y != 0.f) { found = 4 * i + 1; s = v.y; }
        if (v.z != 0.f) { found = 4 * i + 2; s = v.z; }
        if (v.w != 0.f) { found = 4 * i + 3; s = v.w; }
    }
    if (found >= 0) { g_idx[r] = found; g_sgn[r] = s; }   // exactly one thread hits
}

// ---------------- kernel 2: bitonic sort of (idx value, d) ----------------
__global__ void k_sort()
{
    __shared__ int key[Dn];
    int base = blockIdx.x * Dn;               // block 0: C1, block 1: C2
    for (int i = threadIdx.x; i < Dn; i += blockDim.x)
        key[i] = (g_idx[base + i] << 11) | i; // idx<16000 (14b) | d (11b)
    __syncthreads();
    for (int size = 2; size <= Dn; size <<= 1)
        for (int stride = size >> 1; stride > 0; stride >>= 1) {
            for (int t = threadIdx.x; t < Dn; t += blockDim.x) {
                int p = t ^ stride;
                if (p > t) {
                    int a = key[t], c = key[p];
                    bool asc = ((t & size) == 0);
                    if ((a > c) == asc) { key[t] = c; key[p] = a; }
                }
            }
            __syncthreads();
        }
    for (int i = threadIdx.x; i < Dn; i += blockDim.x) {
        int kv = key[i];
        if (blockIdx.x == 0) { g_c1s[i] = kv >> 11; g_j1[i] = kv & (Dn - 1); }
        else                 { g_c2s[i] = kv >> 11; g_j2[i] = kv & (Dn - 1); }
    }
}

// ---------------- kernel 3: build signed, sorted, b-contiguous U / V ----------------
__global__ void k_buildUV(const float* __restrict__ x1, const float* __restrict__ x2)
{
    int j = blockIdx.x;                       // 0..4095
    int b = threadIdx.x;                      // 0..127
    if (j < Dn) {
        int d = g_j1[j];
        g_U[j * Bn + b] = g_sgn[d] * __ldg(x1 + b * Dn + d);
    } else {
        int jj = j - Dn;
        int d = g_j2[jj];
        g_V[jj * Bn + b] = g_sgn[Dn + d] * __ldg(x2 + b * Dn + d);
    }
}

// ---------------- kernel 4: krel-major register-accumulating conv ----------------
// Per CTA: enumerate pairs (binary-search windows), scatter into 16 krel buckets,
// then each warp processes whole runs with float4 lanes (128 batch per pair,
// register accumulator — no per-pair smem RMW chain).
// smem = 8448 (sphi/sc union) + 26624 (buckets) + 64 = 35136 B -> 6 CTAs/SM.
__global__ void __launch_bounds__(128) k_main(float* __restrict__ out)
{
    __shared__ __align__(16) unsigned char s_union[Wn * 132 * 4];  // 8448 B
    __shared__ int sbkt[Wn * BCAP];                                // 26624 B
    __shared__ int scnt[Wn];

    unsigned short* sc1  = (unsigned short*)s_union;        // [0..Dn)
    unsigned short* sc2  = ((unsigned short*)s_union) + Dn; // [Dn..2Dn) = 8192 B used
    float*          sphi = (float*)s_union;                 // reused AFTER sync

    int tid  = threadIdx.x;
    int w    = tid >> 5;
    int lane = tid & 31;
    int k0   = blockIdx.x * Wn;

    for (int t = tid; t < Dn; t += 128) {
        sc1[t] = (unsigned short)g_c1s[t];
        sc2[t] = (unsigned short)g_c2s[t];
    }
    if (tid < Wn) scnt[tid] = 0;
    __syncthreads();

    // ---- enumerate pairs for this chunk and scatter into krel buckets ----
    for (int jj = 0; jj < Dn / 128; jj++) {
        int j   = tid + jj * 128;
        int c1v = sc1[j];
        int a   = k0 - c1v; if (a < 0) a += Pn;        // window start value (mod P)
        int lo = 0, hi = Dn;
        while (lo < hi) { int m = (lo + hi) >> 1; if ((int)sc2[m] < a) lo = m + 1; else hi = m; }
        int cnt;
        if (a + Wn <= Pn) {                            // window does not wrap P
            int lo2 = 0, hi2 = Dn, x = a + Wn;
            while (lo2 < hi2) { int m = (lo2 + hi2) >> 1; if ((int)sc2[m] < x) lo2 = m + 1; else hi2 = m; }
            cnt = lo2 - lo;
        } else {                                       // window wraps past P
            int lo2 = 0, hi2 = Dn, x = a + Wn - Pn;
            while (lo2 < hi2) { int m = (lo2 + hi2) >> 1; if ((int)sc2[m] < x) lo2 = m + 1; else hi2 = m; }
            cnt = (Dn - lo) + lo2;
        }
        for (int t = 0; t < cnt; t++) {
            int i = lo + t; if (i >= Dn) i -= Dn;      // circular sorted run
            int kk = c1v + (int)sc2[i]; if (kk >= Pn) kk -= Pn;
            int krel = kk - k0;                        // in [0, Wn) by construction
            int pos = atomicAdd(&scnt[krel], 1);
            if (pos < BCAP) sbkt[krel * BCAP + pos] = (j << 11) | i;
        }
    }
    __syncthreads();   // buckets complete; sc1/sc2 dead -> sphi may overlay

    // ---- main: warp w owns runs w, w+4, w+8, w+12; register accumulation ----
    for (int r = w; r < Wn; r += 4) {
        int n = scnt[r]; if (n > BCAP) n = BCAP;
        float4 acc = make_float4(0.f, 0.f, 0.f, 0.f);
        const int* bp = sbkt + r * BCAP;
        #pragma unroll 2
        for (int p = 0; p < n; p++) {
            int wrd = bp[p];                            // LDS broadcast (uniform)
            int j = wrd >> 11;
            int i = wrd & (Dn - 1);
            float4 u = __ldg((const float4*)g_U + (j << 5) + lane);  // 128 batch/warp
            float4 v = __ldg((const float4*)g_V + (i << 5) + lane);
            acc.x += u.x * v.x;
            acc.y += u.y * v.y;
            acc.z += u.z * v.z;
            acc.w += u.w * v.w;
        }
        *(float4*)(sphi + r * 132 + 4 * lane) = acc;    // aligned: (132r+4l)%4==0
    }
    __syncthreads();

    // ---- coalesced transposed writeback: thread tid = batch row ----
    float4 o[Wn / 4];
    #pragma unroll
    for (int r = 0; r < Wn; r += 4) {
        o[r >> 2] = make_float4(sphi[(r + 0) * 132 + tid],
                                sphi[(r + 1) * 132 + tid],
                                sphi[(r + 2) * 132 + tid],
                                sphi[(r + 3) * 132 + tid]);
    }
    float4* op = (float4*)(out + (size_t)tid * Pn + k0);  // 16B-aligned (Pn%4==0, k0%16==0)
    #pragma unroll
    for (int q = 0; q < Wn / 4; q++) op[q] = o[q];
}

// ---------------- launch ----------------
extern "C" void kernel_launch(void* const* d_in, const int* in_sizes, int n_in,
                              void* d_out, int out_size)
{
    // Identify inputs by element count, preserving relative order:
    // x1/x2 have B*D = 262144, C1/C2 have D*P = 32768000.
    const float* xs[2] = {nullptr, nullptr};
    const float* Cs[2] = {nullptr, nullptr};
    int nx = 0, nc = 0;
    for (int i = 0; i < n_in; i++) {
        if (in_sizes[i] == Bn * Dn) { if (nx < 2) xs[nx++] = (const float*)d_in[i]; }
        else                        { if (nc < 2) Cs[nc++] = (const float*)d_in[i]; }
    }

    k_extract<<<2 * Dn, 256>>>(Cs[0], Cs[1]);
    k_sort<<<2, 1024>>>();
    k_buildUV<<<2 * Dn, Bn>>>(xs[0], xs[1]);
    k_main<<<NCHUNK, 128>>>((float*)d_out);
}